// round 7
// baseline (speedup 1.0000x reference)
#include <cuda_runtime.h>
#include <cooperative_groups.h>
namespace cg = cooperative_groups;

#define BATCH 64
#define NPTS  8192
#define SGRID 384
#define OUTD  128
#define GRID_BLKS 1024                       // 16 blocks/batch, 256 thr, 2 pts/thr
#define CELLS (BATCH * OUTD * OUTD)          // 1,048,576 cells

__device__ float4 d_scratch[CELLS];          // 16MB, 16B-aligned padded cells
__device__ int2   d_blockmin[GRID_BLKS];

// Single 16B vector reduction — sm_90+; 16B-aligned address.
__device__ __forceinline__ void red_add_v4f32(float* p, float a, float b, float c) {
    asm volatile("red.global.add.v4.f32 [%0], {%1, %2, %3, %4};"
                 :: "l"(p), "f"(a), "f"(b), "f"(c), "f"(0.0f) : "memory");
}

__global__ void __launch_bounds__(256, 7)
k_fused(const float* __restrict__ pc1,
        const float* __restrict__ feat,
        const float* __restrict__ tmat,
        float* __restrict__ out)
{
    const int b    = blockIdx.x >> 4;            // 16 blocks per batch
    const int base = (blockIdx.x & 15) << 9;     // 512 points per block
    __shared__ float stage[4096];                // 16KB compact staging
    __shared__ float M[9];
    __shared__ int s0[8], s1[8], soff0, soff1;

    // ---- phase 1a: zero scratch: 1,048,576 float4 over 262,144 threads ----
    {
        const int gid = blockIdx.x * 256 + threadIdx.x;
        const float4 z = make_float4(0.f, 0.f, 0.f, 0.f);
        #pragma unroll
        for (int i = 0; i < 4; i++)
            d_scratch[(size_t)i * (GRID_BLKS * 256) + gid] = z;
    }

    if (threadIdx.x < 9) M[threadIdx.x] = tmat[b * 9 + threadIdx.x];
    __syncthreads();

    // ---- phase 1b: lattice math (coords stay in registers) ----
    unsigned pk[2];
    int mm0 = 0x7FFFFFFF, mm1 = 0x7FFFFFFF;

    #pragma unroll
    for (int k = 0; k < 2; k++) {
        const int n = base + threadIdx.x + (k << 8);
        const float* p = pc1 + (size_t)b * 3 * NPTS + n;
        const float p0 = p[0], p1 = p[NPTS], p2 = p[2 * NPTS];

        const float e0 = M[0] * p0 + M[1] * p1 + M[2] * p2;
        const float e1 = M[3] * p0 + M[4] * p1 + M[5] * p2;
        const float e2 = M[6] * p0 + M[7] * p1 + M[8] * p2;

        // greedy = round(e/3)*3 (IEEE div + round-half-even, matching jnp)
        const float q0 = rintf(__fdiv_rn(e0, 3.0f));
        const float q1 = rintf(__fdiv_rn(e1, 3.0f));
        const float q2 = rintf(__fdiv_rn(e2, 3.0f));
        const float d0 = e0 - 3.0f * q0;
        const float d1 = e1 - 3.0f * q1;
        const float d2 = e2 - 3.0f * q2;

        const int i0 = (int)q0, i1 = (int)q1, i2 = (int)q2;
        const int rs = i0 + i1 + i2;             // remainder_sum (exact)

        // rank = inverse of stable descending argsort of (d0,d1,d2)
        int rk0 = (d1 > d0) + (d2 > d0);
        int rk1 = (d0 > d1) + (d2 > d1) + (d0 == d1);

        int g0 = 3 * i0;
        int g1 = 3 * i1;

        int sh0 = 0, sh1 = 0;
        if (rs > 0) {
            const int thr = 3 - rs;
            sh0 = (rk0 >= thr) ? -3 : 0;
            sh1 = (rk1 >= thr) ? -3 : 0;
        } else if (rs < 0) {
            sh0 = (rk0 < -rs) ? 3 : 0;
            sh1 = (rk1 < -rs) ? 3 : 0;
        }
        g0 += sh0;  g1 += sh1;
        rk0 += sh0 + rs;
        rk1 += sh1 + rs;

        // JAX gather semantics for CANONICAL[rank]: wrap negatives +3, clamp [0,2]
        int cr0 = (rk0 < 0) ? rk0 + 3 : rk0;  cr0 = min(max(cr0, 0), 2);
        int cr1 = (rk1 < 0) ? rk1 + 3 : rk1;  cr1 = min(max(cr1, 0), 2);

        mm0 = min(mm0, g0 - cr0);   // min_r CANONICAL[cr][r] == -cr
        mm1 = min(mm1, g1 - cr1);

        pk[k] = (unsigned)(g0 + 1024) | ((unsigned)(g1 + 1024) << 16);
    }

    // ---- phase 1c: block min-reduction -> one int2 store ----
    {
        int m0 = mm0, m1 = mm1;
        #pragma unroll
        for (int o = 16; o; o >>= 1) {
            m0 = min(m0, __shfl_xor_sync(0xFFFFFFFFu, m0, o));
            m1 = min(m1, __shfl_xor_sync(0xFFFFFFFFu, m1, o));
        }
        if ((threadIdx.x & 31) == 0) {
            s0[threadIdx.x >> 5] = m0;
            s1[threadIdx.x >> 5] = m1;
        }
        __syncthreads();
        if (threadIdx.x == 0) {
            int a = s0[0], c = s1[0];
            #pragma unroll
            for (int w = 1; w < 8; w++) { a = min(a, s0[w]); c = min(c, s1[w]); }
            d_blockmin[blockIdx.x] = make_int2(a, c);
        }
    }

    cg::this_grid().sync();   // scratch zero + block minima visible

    // ---- phase 2: per-batch offset + one red.v4 per point ----
    if (threadIdx.x < 16) {
        int2 v = d_blockmin[(b << 4) + threadIdx.x];
        int a = v.x, c = v.y;
        #pragma unroll
        for (int o = 8; o; o >>= 1) {
            a = min(a, __shfl_xor_sync(0xFFFFu, a, o));
            c = min(c, __shfl_xor_sync(0xFFFFu, c, o));
        }
        if (threadIdx.x == 0) { soff0 = a; soff1 = c; }
    }
    __syncthreads();
    const int off0 = soff0, off1 = soff1;

    #pragma unroll
    for (int k = 0; k < 2; k++) {
        const int n  = base + threadIdx.x + (k << 8);
        const int g0 = (int)(pk[k] & 0xFFFFu) - 1024;
        const int g1 = (int)(pk[k] >> 16)     - 1024;
        const int row = g0 - off0;        // >= 0 (offset is the min)
        const int col = g1 - off1;
        if (row < SGRID && col < SGRID) {
            const int u = row / 3;        // row ≡ pts_pick0 (mod 3) exactly
            const int v = col / 3;
            const int idx = (b << 14) + (u << 7) + v;
            const float* f = feat + (size_t)b * 3 * NPTS + n;
            red_add_v4f32(&d_scratch[idx].x, f[0], f[NPTS], f[2 * NPTS]);
        }
    }

    cg::this_grid().sync();   // all reds visible

    // ---- phase 3: compact scratch (16B cells) -> out (12B cells) ----
    // Block handles 1024 cells: coalesced float4 loads -> smem, then
    // coalesced float4 stores assembled from smem scalars.
    {
        const int cellBase = blockIdx.x << 10;          // 1024 cells per block
        float4* sg = reinterpret_cast<float4*>(stage);
        #pragma unroll
        for (int k = 0; k < 4; k++)
            sg[(k << 8) + threadIdx.x] = d_scratch[cellBase + (k << 8) + threadIdx.x];
        __syncthreads();

        float4* o4 = reinterpret_cast<float4*>(out) + ((size_t)blockIdx.x * 768);
        #pragma unroll
        for (int k = 0; k < 3; k++) {
            const int q  = (k << 8) + threadIdx.x;      // local out-float4 index
            const int f0 = q << 2;                      // local out-float index
            float4 v;
            v.x = stage[((f0 + 0) / 3) * 4 + (f0 + 0) % 3];
            v.y = stage[((f0 + 1) / 3) * 4 + (f0 + 1) % 3];
            v.z = stage[((f0 + 2) / 3) * 4 + (f0 + 2) % 3];
            v.w = stage[((f0 + 3) / 3) * 4 + (f0 + 3) % 3];
            o4[q] = v;
        }
    }
}

// ---------------------------------------------------------------------------
extern "C" void kernel_launch(void* const* d_in, const int* in_sizes, int n_in,
                              void* d_out, int out_size)
{
    const float* pc1  = (const float*)d_in[0];
    const float* feat = (const float*)d_in[1];
    const float* tmat = (const float*)d_in[2];
    float*       out  = (float*)d_out;

    void* args[] = { (void*)&pc1, (void*)&feat, (void*)&tmat, (void*)&out };
    cudaLaunchCooperativeKernel((const void*)k_fused,
                                dim3(GRID_BLKS), dim3(256), args, 0, 0);
}

// round 8
// speedup vs baseline: 1.0015x; 1.0015x over previous
#include <cuda_runtime.h>
#include <cooperative_groups.h>
namespace cg = cooperative_groups;

#define BATCH 64
#define NPTS  8192
#define SGRID 384
#define OUTD  128
#define GRID_BLKS 1024                       // 16 blocks/batch, 256 thr, 2 pts/thr
#define CELLS (BATCH * OUTD * OUTD)          // 1,048,576 cells

__device__ float4 d_scratch[CELLS];          // 16MB, 16B-aligned padded cells
__device__ int2   d_blockmin[GRID_BLKS];

// Single 16B vector reduction — sm_90+; 16B-aligned address.
__device__ __forceinline__ void red_add_v4f32(float* p, float a, float b, float c) {
    asm volatile("red.global.add.v4.f32 [%0], {%1, %2, %3, %4};"
                 :: "l"(p), "f"(a), "f"(b), "f"(c), "f"(0.0f) : "memory");
}

__global__ void __launch_bounds__(256, 7)
k_fused(const float* __restrict__ pc1,
        const float* __restrict__ feat,
        const float* __restrict__ tmat,
        float* __restrict__ out)
{
    const int b    = blockIdx.x >> 4;            // 16 blocks per batch
    const int base = (blockIdx.x & 15) << 9;     // 512 points per block
    __shared__ float stage[4096];                // 16KB compact staging
    __shared__ float M[9];
    __shared__ int s0[8], s1[8], soff0, soff1;

    // ---- phase 1a: zero scratch: 1,048,576 float4 over 262,144 threads ----
    {
        const int gid = blockIdx.x * 256 + threadIdx.x;
        const float4 z = make_float4(0.f, 0.f, 0.f, 0.f);
        #pragma unroll
        for (int i = 0; i < 4; i++)
            d_scratch[(size_t)i * (GRID_BLKS * 256) + gid] = z;
    }

    if (threadIdx.x < 9) M[threadIdx.x] = tmat[b * 9 + threadIdx.x];
    __syncthreads();

    // ---- phase 1b: lattice math (coords stay in registers) ----
    unsigned pk[2];
    int mm0 = 0x7FFFFFFF, mm1 = 0x7FFFFFFF;

    #pragma unroll
    for (int k = 0; k < 2; k++) {
        const int n = base + threadIdx.x + (k << 8);
        const float* p = pc1 + (size_t)b * 3 * NPTS + n;
        const float p0 = p[0], p1 = p[NPTS], p2 = p[2 * NPTS];

        const float e0 = M[0] * p0 + M[1] * p1 + M[2] * p2;
        const float e1 = M[3] * p0 + M[4] * p1 + M[5] * p2;
        const float e2 = M[6] * p0 + M[7] * p1 + M[8] * p2;

        // greedy = round(e/3)*3 (IEEE div + round-half-even, matching jnp)
        const float q0 = rintf(__fdiv_rn(e0, 3.0f));
        const float q1 = rintf(__fdiv_rn(e1, 3.0f));
        const float q2 = rintf(__fdiv_rn(e2, 3.0f));
        const float d0 = e0 - 3.0f * q0;
        const float d1 = e1 - 3.0f * q1;
        const float d2 = e2 - 3.0f * q2;

        const int i0 = (int)q0, i1 = (int)q1, i2 = (int)q2;
        const int rs = i0 + i1 + i2;             // remainder_sum (exact)

        // rank = inverse of stable descending argsort of (d0,d1,d2)
        int rk0 = (d1 > d0) + (d2 > d0);
        int rk1 = (d0 > d1) + (d2 > d1) + (d0 == d1);

        int g0 = 3 * i0;
        int g1 = 3 * i1;

        int sh0 = 0, sh1 = 0;
        if (rs > 0) {
            const int thr = 3 - rs;
            sh0 = (rk0 >= thr) ? -3 : 0;
            sh1 = (rk1 >= thr) ? -3 : 0;
        } else if (rs < 0) {
            sh0 = (rk0 < -rs) ? 3 : 0;
            sh1 = (rk1 < -rs) ? 3 : 0;
        }
        g0 += sh0;  g1 += sh1;
        rk0 += sh0 + rs;
        rk1 += sh1 + rs;

        // JAX gather semantics for CANONICAL[rank]: wrap negatives +3, clamp [0,2]
        int cr0 = (rk0 < 0) ? rk0 + 3 : rk0;  cr0 = min(max(cr0, 0), 2);
        int cr1 = (rk1 < 0) ? rk1 + 3 : rk1;  cr1 = min(max(cr1, 0), 2);

        mm0 = min(mm0, g0 - cr0);   // min_r CANONICAL[cr][r] == -cr
        mm1 = min(mm1, g1 - cr1);

        pk[k] = (unsigned)(g0 + 1024) | ((unsigned)(g1 + 1024) << 16);
    }

    // ---- phase 1c: block min-reduction -> one int2 store ----
    {
        int m0 = mm0, m1 = mm1;
        #pragma unroll
        for (int o = 16; o; o >>= 1) {
            m0 = min(m0, __shfl_xor_sync(0xFFFFFFFFu, m0, o));
            m1 = min(m1, __shfl_xor_sync(0xFFFFFFFFu, m1, o));
        }
        if ((threadIdx.x & 31) == 0) {
            s0[threadIdx.x >> 5] = m0;
            s1[threadIdx.x >> 5] = m1;
        }
        __syncthreads();
        if (threadIdx.x == 0) {
            int a = s0[0], c = s1[0];
            #pragma unroll
            for (int w = 1; w < 8; w++) { a = min(a, s0[w]); c = min(c, s1[w]); }
            d_blockmin[blockIdx.x] = make_int2(a, c);
        }
    }

    cg::this_grid().sync();   // scratch zero + block minima visible

    // ---- phase 2: per-batch offset + one red.v4 per point ----
    if (threadIdx.x < 16) {
        int2 v = d_blockmin[(b << 4) + threadIdx.x];
        int a = v.x, c = v.y;
        #pragma unroll
        for (int o = 8; o; o >>= 1) {
            a = min(a, __shfl_xor_sync(0xFFFFu, a, o));
            c = min(c, __shfl_xor_sync(0xFFFFu, c, o));
        }
        if (threadIdx.x == 0) { soff0 = a; soff1 = c; }
    }
    __syncthreads();
    const int off0 = soff0, off1 = soff1;

    #pragma unroll
    for (int k = 0; k < 2; k++) {
        const int n  = base + threadIdx.x + (k << 8);
        const int g0 = (int)(pk[k] & 0xFFFFu) - 1024;
        const int g1 = (int)(pk[k] >> 16)     - 1024;
        const int row = g0 - off0;        // >= 0 (offset is the min)
        const int col = g1 - off1;
        if (row < SGRID && col < SGRID) {
            const int u = row / 3;        // row ≡ pts_pick0 (mod 3) exactly
            const int v = col / 3;
            const int idx = (b << 14) + (u << 7) + v;
            const float* f = feat + (size_t)b * 3 * NPTS + n;
            red_add_v4f32(&d_scratch[idx].x, f[0], f[NPTS], f[2 * NPTS]);
        }
    }

    cg::this_grid().sync();   // all reds visible

    // ---- phase 3: compact scratch (16B cells) -> out (12B cells) ----
    // Block handles 1024 cells: coalesced float4 loads -> smem, then
    // coalesced float4 stores assembled from smem scalars.
    {
        const int cellBase = blockIdx.x << 10;          // 1024 cells per block
        float4* sg = reinterpret_cast<float4*>(stage);
        #pragma unroll
        for (int k = 0; k < 4; k++)
            sg[(k << 8) + threadIdx.x] = d_scratch[cellBase + (k << 8) + threadIdx.x];
        __syncthreads();

        float4* o4 = reinterpret_cast<float4*>(out) + ((size_t)blockIdx.x * 768);
        #pragma unroll
        for (int k = 0; k < 3; k++) {
            const int q  = (k << 8) + threadIdx.x;      // local out-float4 index
            const int f0 = q << 2;                      // local out-float index
            float4 v;
            v.x = stage[((f0 + 0) / 3) * 4 + (f0 + 0) % 3];
            v.y = stage[((f0 + 1) / 3) * 4 + (f0 + 1) % 3];
            v.z = stage[((f0 + 2) / 3) * 4 + (f0 + 2) % 3];
            v.w = stage[((f0 + 3) / 3) * 4 + (f0 + 3) % 3];
            o4[q] = v;
        }
    }
}

// ---------------------------------------------------------------------------
extern "C" void kernel_launch(void* const* d_in, const int* in_sizes, int n_in,
                              void* d_out, int out_size)
{
    const float* pc1  = (const float*)d_in[0];
    const float* feat = (const float*)d_in[1];
    const float* tmat = (const float*)d_in[2];
    float*       out  = (float*)d_out;

    void* args[] = { (void*)&pc1, (void*)&feat, (void*)&tmat, (void*)&out };
    cudaLaunchCooperativeKernel((const void*)k_fused,
                                dim3(GRID_BLKS), dim3(256), args, 0, 0);
}

// round 9
// speedup vs baseline: 1.2576x; 1.2557x over previous
#include <cuda_runtime.h>

#define BATCH 64
#define NPTS  8192
#define SGRID 384
#define OUTD  128
#define CELLS (BATCH * OUTD * OUTD)      // 1,048,576 padded cells (float4)

__device__ float4   d_scratch [CELLS];   // 16MB padded accumulation grid
__device__ int2     d_blockmin[BATCH * 32];
__device__ unsigned d_gpack   [BATCH * NPTS];

// Single 16B vector reduction — sm_90+; 16B-aligned address.
__device__ __forceinline__ void red_add_v4f32(float* p, float a, float b, float c) {
    asm volatile("red.global.add.v4.f32 [%0], {%1, %2, %3, %4};"
                 :: "l"(p), "f"(a), "f"(b), "f"(c), "f"(0.0f) : "memory");
}

// ---------------------------------------------------------------------------
// k1: zero scratch + lattice math + gpack + per-block coord min.
// 2048 blocks x 256 threads, 1 point each.
// ---------------------------------------------------------------------------
__global__ void __launch_bounds__(256) k_compute(const float* __restrict__ pc1,
                                                 const float* __restrict__ tmat)
{
    // zero scratch: 1,048,576 float4 over 524,288 threads (2 each)
    {
        const int gid = blockIdx.x * 256 + threadIdx.x;
        const float4 z = make_float4(0.f, 0.f, 0.f, 0.f);
        d_scratch[gid]          = z;
        d_scratch[524288 + gid] = z;
    }

    const int b = blockIdx.x >> 5;
    const int n = ((blockIdx.x & 31) << 8) + threadIdx.x;

    __shared__ float M[9];
    if (threadIdx.x < 9) M[threadIdx.x] = tmat[b * 9 + threadIdx.x];
    __syncthreads();

    const float* p = pc1 + (size_t)b * 3 * NPTS + n;
    const float p0 = p[0], p1 = p[NPTS], p2 = p[2 * NPTS];

    const float e0 = M[0] * p0 + M[1] * p1 + M[2] * p2;
    const float e1 = M[3] * p0 + M[4] * p1 + M[5] * p2;
    const float e2 = M[6] * p0 + M[7] * p1 + M[8] * p2;

    // greedy = round(e/3)*3 (IEEE div + round-half-even, matching jnp)
    const float q0 = rintf(__fdiv_rn(e0, 3.0f));
    const float q1 = rintf(__fdiv_rn(e1, 3.0f));
    const float q2 = rintf(__fdiv_rn(e2, 3.0f));
    const float d0 = e0 - 3.0f * q0;
    const float d1 = e1 - 3.0f * q1;
    const float d2 = e2 - 3.0f * q2;

    const int i0 = (int)q0, i1 = (int)q1, i2 = (int)q2;
    const int rs = i0 + i1 + i2;             // remainder_sum (exact)

    // rank = inverse of stable descending argsort of (d0,d1,d2)
    int rk0 = (d1 > d0) + (d2 > d0);
    int rk1 = (d0 > d1) + (d2 > d1) + (d0 == d1);

    int g0 = 3 * i0;
    int g1 = 3 * i1;

    int sh0 = 0, sh1 = 0;
    if (rs > 0) {
        const int thr = 3 - rs;
        sh0 = (rk0 >= thr) ? -3 : 0;
        sh1 = (rk1 >= thr) ? -3 : 0;
    } else if (rs < 0) {
        sh0 = (rk0 < -rs) ? 3 : 0;
        sh1 = (rk1 < -rs) ? 3 : 0;
    }
    g0 += sh0;  g1 += sh1;
    rk0 += sh0 + rs;
    rk1 += sh1 + rs;

    // JAX gather semantics for CANONICAL[rank]: wrap negatives +3, clamp [0,2]
    int cr0 = (rk0 < 0) ? rk0 + 3 : rk0;  cr0 = min(max(cr0, 0), 2);
    int cr1 = (rk1 < 0) ? rk1 + 3 : rk1;  cr1 = min(max(cr1, 0), 2);

    int m0 = g0 - cr0;   // min_r CANONICAL[cr][r] == -cr
    int m1 = g1 - cr1;

    d_gpack[b * NPTS + n] = (unsigned)(g0 + 1024) | ((unsigned)(g1 + 1024) << 16);

    #pragma unroll
    for (int o = 16; o; o >>= 1) {
        m0 = min(m0, __shfl_xor_sync(0xFFFFFFFFu, m0, o));
        m1 = min(m1, __shfl_xor_sync(0xFFFFFFFFu, m1, o));
    }
    __shared__ int s0[8], s1[8];
    if ((threadIdx.x & 31) == 0) {
        s0[threadIdx.x >> 5] = m0;
        s1[threadIdx.x >> 5] = m1;
    }
    __syncthreads();
    if (threadIdx.x == 0) {
        int a = s0[0], c = s1[0];
        #pragma unroll
        for (int w = 1; w < 8; w++) { a = min(a, s0[w]); c = min(c, s1[w]); }
        d_blockmin[blockIdx.x] = make_int2(a, c);
    }
}

// ---------------------------------------------------------------------------
// k2: per-batch offset + ONE red.v4 per point into padded scratch.
// 2048 blocks x 256 threads, 1 point each.
// ---------------------------------------------------------------------------
__global__ void __launch_bounds__(256) k_scatter(const float* __restrict__ feat)
{
    const int b = blockIdx.x >> 5;
    const int n = ((blockIdx.x & 31) << 8) + threadIdx.x;

    __shared__ int soff0, soff1;
    if (threadIdx.x < 32) {
        int2 v = d_blockmin[b * 32 + threadIdx.x];
        int a = v.x, c = v.y;
        #pragma unroll
        for (int o = 16; o; o >>= 1) {
            a = min(a, __shfl_xor_sync(0xFFFFFFFFu, a, o));
            c = min(c, __shfl_xor_sync(0xFFFFFFFFu, c, o));
        }
        if (threadIdx.x == 0) { soff0 = a; soff1 = c; }
    }

    const unsigned pk = d_gpack[b * NPTS + n];
    const float* f = feat + (size_t)b * 3 * NPTS + n;
    const float f0 = f[0], f1 = f[NPTS], f2 = f[2 * NPTS];

    __syncthreads();
    const int row = ((int)(pk & 0xFFFFu) - 1024) - soff0;   // >= 0
    const int col = ((int)(pk >> 16)     - 1024) - soff1;

    if (row < SGRID && col < SGRID) {
        const int u = row / 3;           // row ≡ pts_pick0 (mod 3) exactly
        const int v = col / 3;
        const int idx = (b << 14) + (u << 7) + v;
        red_add_v4f32(&d_scratch[idx].x, f0, f1, f2);
    }
}

// ---------------------------------------------------------------------------
// k3: compact scratch (16B cells) -> out (12B cells).
// One coalesced float4 store per thread; two overlapping contiguous float4
// loads per thread (warp window ~684B -> high L1 reuse). 3072 blocks x 256.
// ---------------------------------------------------------------------------
__global__ void __launch_bounds__(256) k_compact(float* __restrict__ out)
{
    const int j = blockIdx.x * 256 + threadIdx.x;   // 786432 out-float4
    const int f = 4 * j;
    const int c0 = f / 3;                           // 4j/3, rem = j%3
    const int r  = j % 3;

    const float4 A = d_scratch[c0];
    const float4 B = d_scratch[c0 + 1];

    // 6-float window (A.x A.y A.z B.x B.y B.z), take [r, r+4)
    float4 v;
    v.x = (r == 0) ? A.x : ((r == 1) ? A.y : A.z);
    v.y = (r == 0) ? A.y : ((r == 1) ? A.z : B.x);
    v.z = (r == 0) ? A.z : ((r == 1) ? B.x : B.y);
    v.w = (r == 0) ? B.x : ((r == 1) ? B.y : B.z);

    reinterpret_cast<float4*>(out)[j] = v;
}

// ---------------------------------------------------------------------------
extern "C" void kernel_launch(void* const* d_in, const int* in_sizes, int n_in,
                              void* d_out, int out_size)
{
    const float* pc1  = (const float*)d_in[0];
    const float* feat = (const float*)d_in[1];
    const float* tmat = (const float*)d_in[2];
    float*       out  = (float*)d_out;

    k_compute<<<2048, 256>>>(pc1, tmat);
    k_scatter<<<2048, 256>>>(feat);
    k_compact<<<3072, 256>>>(out);
}